// round 13
// baseline (speedup 1.0000x reference)
#include <cuda_runtime.h>
#include <cuda_fp16.h>
#include <cstdint>

// ============================================================================
// TensorDense via explicit-W:  out = relu(x @ W + bias)
//   W[(i,j,k),(a,b,c)] = sum_q (sum_p c1[i,a,p] c2[j,b,p,q]) c3[k,c,q]
// Single-product fp16 GEMM (mma.sync m16n8k16, fp32 accum) at the measured
// legacy-HMMA instruction-rate ceiling (~242us). Prep path co-schedules the
// independent x->fp16 conversion with w12 (launch 1) and assemble (launch 2)
// so neither launch leaves SMs idle.
// ============================================================================

#define MODE 16
#define KDIM 4096
#define NDIM 4096
#define BATCH 2048

__device__ float  g_W12[256 * 256 * 32];            // [ia][jb][q]  8MB
__device__ __half g_xh[(size_t)BATCH * KDIM];
__device__ __half g_wh[(size_t)NDIM * KDIM];        // W^T [n][k], fp16

// total x packs (uint4 = 8 halves): 2048*4096/8 = 1,048,576; half = 524,288
#define XPACKS_HALF 524288

// ---------------------------------------------------------------------------
// helpers (sm_80/sm_90-era only; ptxas targets bare sm_103)
// ---------------------------------------------------------------------------
__device__ __forceinline__ uint32_t smem_u32(const void* p) {
    uint32_t a;
    asm("{ .reg .u64 t; cvta.to.shared.u64 t, %1; cvt.u32.u64 %0, t; }"
        : "=r"(a) : "l"(p));
    return a;
}
__device__ __forceinline__ void cp_async16(uint32_t s, const void* g) {
    asm volatile("cp.async.cg.shared.global [%0], [%1], 16;" :: "r"(s), "l"(g));
}
#define CP_COMMIT() asm volatile("cp.async.commit_group;" ::: "memory")
#define CP_WAIT1()  asm volatile("cp.async.wait_group 1;"  ::: "memory")

__device__ __forceinline__ void ldmx4(uint32_t* r, uint32_t addr) {
    asm volatile("ldmatrix.sync.aligned.m8n8.x4.shared.b16 {%0,%1,%2,%3}, [%4];"
                 : "=r"(r[0]), "=r"(r[1]), "=r"(r[2]), "=r"(r[3]) : "r"(addr));
}
__device__ __forceinline__ void mma_f16(float* c, const uint32_t* a,
                                        uint32_t b0, uint32_t b1) {
    asm volatile(
        "mma.sync.aligned.m16n8k16.row.col.f32.f16.f16.f32 "
        "{%0,%1,%2,%3}, {%4,%5,%6,%7}, {%8,%9}, {%0,%1,%2,%3};"
        : "+f"(c[0]), "+f"(c[1]), "+f"(c[2]), "+f"(c[3])
        : "r"(a[0]), "r"(a[1]), "r"(a[2]), "r"(a[3]), "r"(b0), "r"(b1));
}
__device__ __forceinline__ uint32_t h2_as_u32(__half2 h) {
    uint32_t u;
    memcpy(&u, &h, 4);
    return u;
}
// convert 2 float4 (8 floats) -> one uint4 of halves, store at pack p
__device__ __forceinline__ void cvt_pack(const float* __restrict__ x, size_t p) {
    float4 v0 = reinterpret_cast<const float4*>(x)[p * 2 + 0];
    float4 v1 = reinterpret_cast<const float4*>(x)[p * 2 + 1];
    uint4 o;
    o.x = h2_as_u32(__floats2half2_rn(v0.x, v0.y));
    o.y = h2_as_u32(__floats2half2_rn(v0.z, v0.w));
    o.z = h2_as_u32(__floats2half2_rn(v1.x, v1.y));
    o.w = h2_as_u32(__floats2half2_rn(v1.z, v1.w));
    reinterpret_cast<uint4*>(g_xh)[p] = o;
}

// ---------------------------------------------------------------------------
// Launch 1: blocks [0,256): W12[ia][jb][q] (CTA per jb);
//           blocks [256,1280): x -> fp16, first half.
// ---------------------------------------------------------------------------
__global__ void prep1_kernel(const float* __restrict__ x,
                             const float* __restrict__ c1,
                             const float* __restrict__ c2) {
    const int tid = threadIdx.x;

    if (blockIdx.x >= 256) {
        const size_t blk = (size_t)(blockIdx.x - 256);
#pragma unroll
        for (int u = 0; u < 2; ++u)
            cvt_pack(x, blk * 512 + (size_t)u * 256 + tid);
        return;
    }

    // ---- W12: CTA per jb, thread per ia ----
    __shared__ float sc2[1024];
    const int jb = blockIdx.x;

    reinterpret_cast<float4*>(sc2)[tid] =
        reinterpret_cast<const float4*>(c2 + (size_t)jb * 1024)[tid];

    float4 c1v[8];
    const float4* c1p = reinterpret_cast<const float4*>(c1 + tid * 32);
#pragma unroll
    for (int u = 0; u < 8; ++u) c1v[u] = c1p[u];
    __syncthreads();

    float4 acc[8];
#pragma unroll
    for (int u = 0; u < 8; ++u) acc[u] = make_float4(0.f, 0.f, 0.f, 0.f);

    const float4* sc2v = reinterpret_cast<const float4*>(sc2);
    const float* c1s = reinterpret_cast<const float*>(c1v);
#pragma unroll
    for (int p = 0; p < 32; ++p) {
        const float cp = c1s[p];
#pragma unroll
        for (int q4 = 0; q4 < 8; ++q4) {
            float4 w = sc2v[p * 8 + q4];          // warp broadcast
            acc[q4].x = fmaf(cp, w.x, acc[q4].x);
            acc[q4].y = fmaf(cp, w.y, acc[q4].y);
            acc[q4].z = fmaf(cp, w.z, acc[q4].z);
            acc[q4].w = fmaf(cp, w.w, acc[q4].w);
        }
    }
    float4* outp = reinterpret_cast<float4*>(g_W12 + ((size_t)tid * 256 + jb) * 32);
#pragma unroll
    for (int u = 0; u < 8; ++u) outp[u] = acc[u];
}

// ---------------------------------------------------------------------------
// Launch 2: blocks [0,1024): assemble W^T fp16, CTA per (i,j,c-quarter);
//           blocks [1024,2048): x -> fp16, second half.
// ---------------------------------------------------------------------------
__global__ void prep2_kernel(const float* __restrict__ x,
                             const float* __restrict__ c3) {
    const int tid = threadIdx.x;

    if (blockIdx.x >= 1024) {
        const size_t blk = (size_t)(blockIdx.x - 1024);
#pragma unroll
        for (int u = 0; u < 2; ++u)
            cvt_pack(x, XPACKS_HALF + blk * 512 + (size_t)u * 256 + tid);
        return;
    }

    __shared__ float sc3[2048];               // [kz][cc][q] for 4 c's
    const int ij = blockIdx.x >> 2;
    const int cg = blockIdx.x & 3;
    const int a = tid >> 4, b = tid & 15;
    const int i = ij >> 4, j = ij & 15;

    // stage c3 rows c = cg*4 .. cg*4+3 for all kz (512 float4)
    {
        const float4* c3g = reinterpret_cast<const float4*>(c3);
        float4* dst = reinterpret_cast<float4*>(sc3);
#pragma unroll
        for (int u = 0; u < 2; ++u) {
            const int e4 = u * 256 + tid;          // 0..511
            const int kz = e4 >> 5, rem4 = e4 & 31;
            dst[e4] = c3g[kz * 128 + cg * 32 + rem4];
        }
    }

    // W12 row for this (ia, jb) in registers
    float4 w12q[8];
    const float4* wp = reinterpret_cast<const float4*>(
        g_W12 + ((size_t)(i * 16 + a) * 256 + (j * 16 + b)) * 32);
#pragma unroll
    for (int u = 0; u < 8; ++u) w12q[u] = wp[u];
    __syncthreads();

    const float4* sc3v = reinterpret_cast<const float4*>(sc3);
#pragma unroll
    for (int cc = 0; cc < 4; ++cc) {
        float acc[16];
#pragma unroll
        for (int kz = 0; kz < 16; ++kz) acc[kz] = 0.f;
#pragma unroll
        for (int q4 = 0; q4 < 8; ++q4) {
            const float4 w = w12q[q4];
#pragma unroll
            for (int kz = 0; kz < 16; ++kz) {
                float4 cv = sc3v[(kz * 4 + cc) * 8 + q4];   // warp broadcast
                acc[kz] = fmaf(w.x, cv.x, acc[kz]);
                acc[kz] = fmaf(w.y, cv.y, acc[kz]);
                acc[kz] = fmaf(w.z, cv.z, acc[kz]);
                acc[kz] = fmaf(w.w, cv.w, acc[kz]);
            }
        }
        __half2 hv[8];
#pragma unroll
        for (int u = 0; u < 8; ++u)
            hv[u] = __floats2half2_rn(acc[u * 2], acc[u * 2 + 1]);
        __half* dst = g_wh + (size_t)(tid * 16 + cg * 4 + cc) * KDIM + ij * 16;
        uint4 o0, o1;
        memcpy(&o0, &hv[0], 16);
        memcpy(&o1, &hv[4], 16);
        reinterpret_cast<uint4*>(dst)[0] = o0;
        reinterpret_cast<uint4*>(dst)[1] = o1;
    }
}

// ---------------------------------------------------------------------------
// Launch 3: single-product fp16 GEMM (best measured mainloop, 242.4us).
// CTA tile 128x128, 4 warps (2m x 2n), warp tile 64x64, BK=64,
// 3-stage cp.async ring, one sync/stage, 2 CTAs/SM.
// SMEM rows: 128B data + 16B pad = 144B (conflict-free ldmatrix).
// ---------------------------------------------------------------------------
#define BM 128
#define BN 128
#define ROWB 144
#define ARR_BYTES (128 * ROWB)            // 18432
#define STAGE_BYTES (2 * ARR_BYTES)       // xh | wh = 36864
#define STAGES 3
#define DYN_BYTES (STAGES * STAGE_BYTES)  // 110592

__global__ __launch_bounds__(128, 2)
void tt_gemm_f16(const float* __restrict__ bias, float* __restrict__ C) {
    extern __shared__ __align__(16) char dyn[];
    const uint32_t dynU = smem_u32(dyn);

    const int tid = threadIdx.x;
    const int wid = tid >> 5;
    const int lid = tid & 31;
    const int warp_m = wid & 1;      // 2 m-groups of 64 rows
    const int warp_n = wid >> 1;     // 2 n-groups of 64 cols
    const int m0 = blockIdx.y * BM;
    const int n0 = blockIdx.x * BN;

    const char* xh = (const char*)g_xh;
    const char* wh = (const char*)g_wh;

    uint32_t sOff[8];
    size_t gAOff[8], gBOff[8];
#pragma unroll
    for (int u = 0; u < 8; ++u) {
        const int ci = u * 128 + tid;
        const int r = ci >> 3, ch = (ci & 7) * 16;
        sOff[u] = (uint32_t)(r * ROWB + ch);
        gAOff[u] = (size_t)(m0 + r) * (KDIM * 2) + ch;
        gBOff[u] = (size_t)(n0 + r) * (KDIM * 2) + ch;
    }

    float acc[4][8][4];
#pragma unroll
    for (int a = 0; a < 4; ++a)
#pragma unroll
        for (int b = 0; b < 8; ++b)
#pragma unroll
            for (int c = 0; c < 4; ++c) acc[a][b][c] = 0.f;

    const uint32_t lmRow = (uint32_t)(lid & 15);
    const uint32_t lmCol = (uint32_t)((lid >> 4) * 16);
    const uint32_t aLM = (uint32_t)((warp_m * 64 + lmRow) * ROWB) + lmCol;
    const uint32_t bLM = (uint32_t)((warp_n * 64 + lmRow) * ROWB) + lmCol;

    auto load_stage = [&](int kt) {
        const uint32_t sb = dynU + (uint32_t)(kt % STAGES) * STAGE_BYTES;
        const size_t ko = (size_t)kt * 128;   // 64 halves = 128B along k
#pragma unroll
        for (int u = 0; u < 8; ++u) {
            cp_async16(sb + sOff[u],             xh + gAOff[u] + ko);
            cp_async16(sb + ARR_BYTES + sOff[u], wh + gBOff[u] + ko);
        }
    };

    load_stage(0); CP_COMMIT();
    load_stage(1); CP_COMMIT();

    const int numK = KDIM / 64;      // 64 stages
    for (int kt = 0; kt < numK; ++kt) {
        CP_WAIT1();
        __syncthreads();             // publish stage kt

        if (kt + 2 < numK) load_stage(kt + 2);
        CP_COMMIT();

        const uint32_t sb = dynU + (uint32_t)(kt % STAGES) * STAGE_BYTES;
        const uint32_t aB = sb + aLM;
        const uint32_t bB = sb + ARR_BYTES + bLM;

#pragma unroll
        for (int ks = 0; ks < 4; ++ks) {             // four k16 steps
            const uint32_t kb = (uint32_t)(ks * 32); // 16 halves = 32B
            uint32_t ah[4][4];
#pragma unroll
            for (int mt = 0; mt < 4; ++mt)
                ldmx4(ah[mt], aB + (uint32_t)(mt * 16 * ROWB) + kb);
            uint32_t bh[4][4];
#pragma unroll
            for (int bt = 0; bt < 4; ++bt)
                ldmx4(bh[bt], bB + (uint32_t)(bt * 16 * ROWB) + kb);
#pragma unroll
            for (int mt = 0; mt < 4; ++mt) {
#pragma unroll
                for (int nt = 0; nt < 8; ++nt) {
                    const int bt = nt >> 1, o = nt & 1;
                    mma_f16(acc[mt][nt], ah[mt], bh[bt][o], bh[bt][o + 2]);
                }
            }
        }
    }

    // epilogue: bias + relu, float2 stores
    const int g = lid >> 2, t4 = lid & 3;
    float bb[8][2];
#pragma unroll
    for (int nt = 0; nt < 8; ++nt) {
        const int col = n0 + warp_n * 64 + nt * 8 + t4 * 2;
        bb[nt][0] = bias[col];
        bb[nt][1] = bias[col + 1];
    }
#pragma unroll
    for (int mt = 0; mt < 4; ++mt) {
        const int row = m0 + warp_m * 64 + mt * 16 + g;
#pragma unroll
        for (int nt = 0; nt < 8; ++nt) {
            const int col = n0 + warp_n * 64 + nt * 8 + t4 * 2;
            float2 v0, v1;
            v0.x = fmaxf(acc[mt][nt][0] + bb[nt][0], 0.f);
            v0.y = fmaxf(acc[mt][nt][1] + bb[nt][1], 0.f);
            v1.x = fmaxf(acc[mt][nt][2] + bb[nt][0], 0.f);
            v1.y = fmaxf(acc[mt][nt][3] + bb[nt][1], 0.f);
            *reinterpret_cast<float2*>(&C[(size_t)row * NDIM + col]) = v0;
            *reinterpret_cast<float2*>(&C[(size_t)(row + 8) * NDIM + col]) = v1;
        }
    }
}

// ---------------------------------------------------------------------------
// Launch
// ---------------------------------------------------------------------------
extern "C" void kernel_launch(void* const* d_in, const int* in_sizes, int n_in,
                              void* d_out, int out_size) {
    const float* x    = (const float*)d_in[0];
    const float* c1   = (const float*)d_in[1];
    const float* c2   = (const float*)d_in[2];
    const float* c3   = (const float*)d_in[3];
    const float* bias = (const float*)d_in[4];
    float* out = (float*)d_out;
    (void)in_sizes; (void)n_in; (void)out_size;

    cudaFuncSetAttribute(tt_gemm_f16,
                         cudaFuncAttributeMaxDynamicSharedMemorySize, DYN_BYTES);

    prep1_kernel<<<256 + 1024, 256>>>(x, c1, c2);   // w12 + cvt half A
    prep2_kernel<<<1024 + 1024, 256>>>(x, c3);      // assemble + cvt half B

    dim3 grid(NDIM / BN, BATCH / BM);   // (32, 16) = 512 CTAs
    tt_gemm_f16<<<grid, 128, DYN_BYTES>>>(bias, out);
}